// round 1
// baseline (speedup 1.0000x reference)
#include <cuda_runtime.h>
#include <cstdint>

// Problem-structure constants (from reference): R ratings, Bu basis units.
#define RR 5
#define BU 4
#define MAX_IN 1024
#define MAX_MU 64
#define MAX_OUT 256
#define MAX_N 50000

// Scratch (static __device__ — no allocation allowed)
__device__ float g_W[RR * MAX_IN * MAX_MU];           // 1.3 MB : W[r] = att[r] @ basis
__device__ float g_P[RR * 3 * MAX_IN * MAX_OUT];      // 15.7 MB: P[r][k] = W[r] @ fc_w block
__device__ float g_m[(size_t)MAX_N * MAX_OUT];        // 51.2 MB: per-(r,type) node messages

// ---------------------------------------------------------------------------
// W[r][i][m] = sum_b att[r,b] * basis[b,i,m]
__global__ void k_W(const float* __restrict__ att, const float* __restrict__ basis,
                    int IN, int MU) {
    int idx = blockIdx.x * blockDim.x + threadIdx.x;
    int total = RR * IN * MU;
    if (idx >= total) return;
    int m = idx % MU;
    int i = (idx / MU) % IN;
    int r = idx / (MU * IN);
    float acc = 0.f;
#pragma unroll
    for (int b = 0; b < BU; b++)
        acc += att[r * BU + b] * basis[(b * IN + i) * MU + m];
    g_W[idx] = acc;
}

// ---------------------------------------------------------------------------
// P[rk][i][o] = sum_m W[r][i][m] * fc_w[(rk*MU + m)*OUT + o],  rk = r*3+k
// One block per (rk, i); blockDim = OUT. fc block (64 KB) is L1/L2 resident.
__global__ void k_P(const float* __restrict__ fc_w, int IN, int MU, int OUT) {
    int o  = threadIdx.x;
    int i  = blockIdx.x % IN;
    int rk = blockIdx.x / IN;
    const float* wrow = g_W + ((size_t)(rk / 3) * IN + i) * MU;
    const float* fcb  = fc_w + (size_t)(rk * MU) * OUT + o;
    float acc = 0.f;
#pragma unroll 8
    for (int m = 0; m < MU; m++)
        acc = fmaf(wrow[m], fcb[(size_t)m * OUT], acc);
    g_P[((size_t)rk * IN + i) * OUT + o] = acc;
}

// ---------------------------------------------------------------------------
// m[n][:] = cj[n] * (P[r,0][f0] + P[r,1][f1] + P[r,2][f2])   (one warp per node)
__global__ void k_m(const int* __restrict__ feat, const float* __restrict__ cj,
                    int r, int N, int IN, int OUT) {
    int w = (blockIdx.x * blockDim.x + threadIdx.x) >> 5;
    int lane = threadIdx.x & 31;
    if (w >= N) return;
    int f0 = feat[w * 3 + 0];
    int f1 = feat[w * 3 + 1];
    int f2 = feat[w * 3 + 2];
    float c = cj[w];
    int OUT4 = OUT >> 2;
    const float4* p0 = (const float4*)(g_P + ((size_t)(r * 3 + 0) * IN + f0) * OUT);
    const float4* p1 = (const float4*)(g_P + ((size_t)(r * 3 + 1) * IN + f1) * OUT);
    const float4* p2 = (const float4*)(g_P + ((size_t)(r * 3 + 2) * IN + f2) * OUT);
    float4* dst = (float4*)(g_m + (size_t)w * OUT);
    for (int j = lane; j < OUT4; j += 32) {
        float4 a = p0[j], b = p1[j], d = p2[j];
        float4 v;
        v.x = c * (a.x + b.x + d.x);
        v.y = c * (a.y + b.y + d.y);
        v.z = c * (a.z + b.z + d.z);
        v.w = c * (a.w + b.w + d.w);
        dst[j] = v;
    }
}

// ---------------------------------------------------------------------------
// For each edge e: out_half[sidx[e]] += m[gidx[e]]     (one warp per edge)
// Vectorized no-return reduction: red.global.add.v4.f32
__global__ void k_scatter(const int* __restrict__ gidx, const int* __restrict__ sidx,
                          float* __restrict__ out_half, int E, int OUT) {
    int w = (blockIdx.x * blockDim.x + threadIdx.x) >> 5;
    int lane = threadIdx.x & 31;
    if (w >= E) return;
    int s = gidx[w];
    int d = sidx[w];
    int OUT4 = OUT >> 2;
    const float4* m = (const float4*)(g_m + (size_t)s * OUT);
    float* ob = out_half + (size_t)d * OUT;
    for (int j = lane; j < OUT4; j += 32) {
        float4 v = m[j];
        float* p = ob + 4 * j;
        asm volatile("red.global.add.v4.f32 [%0], {%1, %2, %3, %4};"
                     :: "l"(p), "f"(v.x), "f"(v.y), "f"(v.z), "f"(v.w)
                     : "memory");
    }
}

// ---------------------------------------------------------------------------
// out = out * ci(row) + bias(col), over both halves [drug | dis]
__global__ void k_fin(float* __restrict__ out,
                      const float* __restrict__ ci_drug, const float* __restrict__ ci_dis,
                      const float* __restrict__ bias, int N, int OUT) {
    long long idx = (long long)blockIdx.x * blockDim.x + threadIdx.x;
    long long total = 2LL * N * OUT;
    if (idx >= total) return;
    int o = (int)(idx % OUT);
    long long row = idx / OUT;
    int n = (int)(row % N);
    int half = (int)(row / N);
    float ci = half ? ci_dis[n] : ci_drug[n];
    out[idx] = out[idx] * ci + bias[o];
}

// ---------------------------------------------------------------------------
extern "C" void kernel_launch(void* const* d_in, const int* in_sizes, int n_in,
                              void* d_out, int out_size) {
    const int*   drug_feat = (const int*)d_in[0];
    const int*   dis_feat  = (const int*)d_in[1];
    const int*   src       = (const int*)d_in[2];
    const int*   dst       = (const int*)d_in[3];
    const float* cj_drug   = (const float*)d_in[4];
    const float* ci_drug   = (const float*)d_in[5];
    const float* cj_dis    = (const float*)d_in[6];
    const float* ci_dis    = (const float*)d_in[7];
    const float* att       = (const float*)d_in[8];
    const float* basis     = (const float*)d_in[9];
    const float* fc_w      = (const float*)d_in[10];
    const float* fc_b      = (const float*)d_in[11];
    float* out = (float*)d_out;

    const int N   = in_sizes[4];                 // nodes (cj_drug has N elements)
    const int E   = in_sizes[2] / RR;            // edges per rating
    const int OUT = in_sizes[11];                // output units (fc_b)
    const int MU  = in_sizes[10] / (OUT * 3 * RR);
    const int IN  = in_sizes[9] / (BU * MU);

    // 0. zero accumulators (out is poisoned by harness)
    cudaMemsetAsync(d_out, 0, (size_t)out_size * sizeof(float), 0);

    // 1. W = att @ basis
    {
        int total = RR * IN * MU;
        k_W<<<(total + 255) / 256, 256>>>(att, basis, IN, MU);
    }
    // 2. P[rk] = W[r] @ fc_w block  (fused FC projection)
    k_P<<<RR * 3 * IN, OUT>>>(fc_w, IN, MU, OUT);

    const int mBlocks = (int)(((long long)N * 32 + 255) / 256);
    const int sBlocks = (int)(((long long)E * 32 + 255) / 256);
    float* out_drug = out;
    float* out_dis  = out + (size_t)N * OUT;

    // 3a. drug -> dis: messages from drug nodes, scatter by dst into dis half
    for (int r = 0; r < RR; r++) {
        k_m<<<mBlocks, 256>>>(drug_feat, cj_drug, r, N, IN, OUT);
        k_scatter<<<sBlocks, 256>>>(src + (size_t)r * E, dst + (size_t)r * E,
                                    out_dis, E, OUT);
    }
    // 3b. dis -> drug: messages from dis nodes (gather by dst), scatter by src
    for (int r = 0; r < RR; r++) {
        k_m<<<mBlocks, 256>>>(dis_feat, cj_dis, r, N, IN, OUT);
        k_scatter<<<sBlocks, 256>>>(dst + (size_t)r * E, src + (size_t)r * E,
                                    out_drug, E, OUT);
    }

    // 4. finalize: *ci, +bias
    {
        long long total = 2LL * N * OUT;
        k_fin<<<(int)((total + 255) / 256), 256>>>(out, ci_drug, ci_dis, fc_b, N, OUT);
    }
}

// round 2
// speedup vs baseline: 1.4760x; 1.4760x over previous
#include <cuda_runtime.h>
#include <cstdint>

#define RR 5
#define BU 4
#define MAX_IN 1024
#define MAX_MU 64
#define MAX_OUT 256
#define MAX_N 50000
#define MAX_E 500000
#define NPART (2 * RR)                       // (direction, rating) partitions
#define NBINS (NPART * MAX_N)                // 500000 histogram bins

// Static scratch (no allocation allowed)
__device__ float g_W[RR * MAX_IN * MAX_MU];            // 1.3 MB
__device__ float g_P[RR * 3 * MAX_IN * MAX_OUT];       // 15.7 MB
__device__ float g_m[(size_t)MAX_N * MAX_OUT];         // 51.2 MB node messages
__device__ int   g_cnt[NBINS];                         // per-bin counts
__device__ int   g_off[NBINS + 1];                     // exclusive offsets (global)
__device__ int   g_cur[NBINS];                         // placement cursors
__device__ int   g_pay[NPART * MAX_E];                 // CSR payload (source node ids)
__device__ int   g_bsum[1024];                         // scan block sums (977 used)

// ---------------------------------------------------------------------------
// W[r][i][m] = sum_b att[r,b] * basis[b,i,m]
__global__ void k_W(const float* __restrict__ att, const float* __restrict__ basis,
                    int IN, int MU) {
    int idx = blockIdx.x * blockDim.x + threadIdx.x;
    int total = RR * IN * MU;
    if (idx >= total) return;
    int m = idx % MU;
    int i = (idx / MU) % IN;
    int r = idx / (MU * IN);
    float acc = 0.f;
#pragma unroll
    for (int b = 0; b < BU; b++)
        acc += att[r * BU + b] * basis[(b * IN + i) * MU + m];
    g_W[idx] = acc;
}

// P[rk][i][o] = sum_m W[r][i][m] * fc_w[(rk*MU+m)*OUT + o]
__global__ void k_P(const float* __restrict__ fc_w, int IN, int MU, int OUT) {
    int o  = threadIdx.x;
    int i  = blockIdx.x % IN;
    int rk = blockIdx.x / IN;
    const float* wrow = g_W + ((size_t)(rk / 3) * IN + i) * MU;
    const float* fcb  = fc_w + (size_t)(rk * MU) * OUT + o;
    float acc = 0.f;
#pragma unroll 8
    for (int m = 0; m < MU; m++)
        acc = fmaf(wrow[m], fcb[(size_t)m * OUT], acc);
    g_P[((size_t)rk * IN + i) * OUT + o] = acc;
}

// ---------------------------------------------------------------------------
// CSR build: zero, histogram, 2-level exclusive scan, place
__global__ void k_zero(int n) {
    int i = blockIdx.x * blockDim.x + threadIdx.x;
    if (i < n) g_cnt[i] = 0;
}

__global__ void k_hist(const int* __restrict__ src, const int* __restrict__ dst,
                       int E, int N) {
    int idx = blockIdx.x * blockDim.x + threadIdx.x;
    if (idx >= NPART * E) return;
    int e = idx % E;
    int p = idx / E;          // p = dir*RR + r
    int r = p % RR;
    int key = (p < RR) ? dst[(size_t)r * E + e] : src[(size_t)r * E + e];
    atomicAdd(&g_cnt[p * N + key], 1);
}

// scan level 1: 512-elem blocks, inclusive scan -> g_off (temp), blocksum -> g_bsum
__global__ void k_scan1(int n) {
    __shared__ int sh[512];
    int tid = threadIdx.x;
    int i = blockIdx.x * 512 + tid;
    int v = (i < n) ? g_cnt[i] : 0;
    sh[tid] = v;
    __syncthreads();
#pragma unroll
    for (int ofs = 1; ofs < 512; ofs <<= 1) {
        int t = (tid >= ofs) ? sh[tid - ofs] : 0;
        __syncthreads();
        sh[tid] += t;
        __syncthreads();
    }
    if (i < n) g_off[i] = sh[tid];            // inclusive, temp
    if (tid == 511) g_bsum[blockIdx.x] = sh[511];
}

// scan level 2: single block inclusive scan of block sums (nb <= 1024)
__global__ void k_scan2(int nb) {
    __shared__ int sh[1024];
    int tid = threadIdx.x;
    sh[tid] = (tid < nb) ? g_bsum[tid] : 0;
    __syncthreads();
#pragma unroll
    for (int ofs = 1; ofs < 1024; ofs <<= 1) {
        int t = (tid >= ofs) ? sh[tid - ofs] : 0;
        __syncthreads();
        sh[tid] += t;
        __syncthreads();
    }
    if (tid < nb) g_bsum[tid] = sh[tid];
}

// scan level 3: finalize exclusive offsets + cursors + sentinel
__global__ void k_scan3(int n) {
    int i = blockIdx.x * blockDim.x + threadIdx.x;
    if (i >= n) return;
    int blk = i >> 9;
    int excl = g_off[i] - g_cnt[i] + (blk ? g_bsum[blk - 1] : 0);
    g_off[i] = excl;
    g_cur[i] = excl;
    if (i == n - 1) g_off[n] = excl + g_cnt[i];
}

__global__ void k_place(const int* __restrict__ src, const int* __restrict__ dst,
                        int E, int N) {
    int idx = blockIdx.x * blockDim.x + threadIdx.x;
    if (idx >= NPART * E) return;
    int e = idx % E;
    int p = idx / E;
    int r = p % RR;
    int key, pay;
    if (p < RR) { key = dst[(size_t)r * E + e]; pay = src[(size_t)r * E + e]; }
    else        { key = src[(size_t)r * E + e]; pay = dst[(size_t)r * E + e]; }
    int pos = atomicAdd(&g_cur[p * N + key], 1);
    g_pay[pos] = pay;
}

// ---------------------------------------------------------------------------
// m[n][:] = cj[n] * (P[r,0][f0] + P[r,1][f1] + P[r,2][f2])   (one warp per node)
__global__ void k_m(const int* __restrict__ feat, const float* __restrict__ cj,
                    int r, int N, int IN, int OUT) {
    int w = (blockIdx.x * blockDim.x + threadIdx.x) >> 5;
    int lane = threadIdx.x & 31;
    if (w >= N) return;
    int f0 = feat[w * 3 + 0];
    int f1 = feat[w * 3 + 1];
    int f2 = feat[w * 3 + 2];
    float c = cj[w];
    int OUT4 = OUT >> 2;
    const float4* p0 = (const float4*)(g_P + ((size_t)(r * 3 + 0) * IN + f0) * OUT);
    const float4* p1 = (const float4*)(g_P + ((size_t)(r * 3 + 1) * IN + f1) * OUT);
    const float4* p2 = (const float4*)(g_P + ((size_t)(r * 3 + 2) * IN + f2) * OUT);
    float4* dstp = (float4*)(g_m + (size_t)w * OUT);
    for (int j = lane; j < OUT4; j += 32) {
        float4 a = p0[j], b = p1[j], d = p2[j];
        float4 v;
        v.x = c * (a.x + b.x + d.x);
        v.y = c * (a.y + b.y + d.y);
        v.z = c * (a.z + b.z + d.z);
        v.w = c * (a.w + b.w + d.w);
        dstp[j] = v;
    }
}

// ---------------------------------------------------------------------------
// Gather: one warp per (node, 128-col half). Accumulate in-edge m rows in
// registers, one non-atomic RMW of the out row slice.
__global__ void k_gather(int p, float* __restrict__ outh, int N) {
    int gw = (blockIdx.x * blockDim.x + threadIdx.x) >> 5;
    int lane = threadIdx.x & 31;
    if (gw >= 2 * N) return;
    int d    = gw >> 1;
    int half = gw & 1;
    int col  = half * 32 + lane;                       // float4 index within 64

    const int* offb = g_off + p * N;
    int s0 = offb[d];
    int s1 = offb[d + 1];

    const float4* mb = (const float4*)g_m;
    float4 acc  = make_float4(0.f, 0.f, 0.f, 0.f);
    float4 acc2 = make_float4(0.f, 0.f, 0.f, 0.f);

    int j = s0;
    for (; j + 1 < s1; j += 2) {
        int sa = g_pay[j];
        int sb = g_pay[j + 1];
        float4 va = mb[(size_t)sa * 64 + col];
        float4 vb = mb[(size_t)sb * 64 + col];
        acc.x += va.x;  acc.y += va.y;  acc.z += va.z;  acc.w += va.w;
        acc2.x += vb.x; acc2.y += vb.y; acc2.z += vb.z; acc2.w += vb.w;
    }
    if (j < s1) {
        int sa = g_pay[j];
        float4 va = mb[(size_t)sa * 64 + col];
        acc.x += va.x; acc.y += va.y; acc.z += va.z; acc.w += va.w;
    }
    acc.x += acc2.x; acc.y += acc2.y; acc.z += acc2.z; acc.w += acc2.w;

    float4* op = (float4*)(outh + (size_t)d * 256) + col;
    float4 cur = *op;
    cur.x += acc.x; cur.y += acc.y; cur.z += acc.z; cur.w += acc.w;
    *op = cur;
}

// ---------------------------------------------------------------------------
__global__ void k_fin(float* __restrict__ out,
                      const float* __restrict__ ci_drug, const float* __restrict__ ci_dis,
                      const float* __restrict__ bias, int N, int OUT) {
    long long idx = (long long)blockIdx.x * blockDim.x + threadIdx.x;
    long long total = 2LL * N * OUT;
    if (idx >= total) return;
    int o = (int)(idx % OUT);
    long long row = idx / OUT;
    int n = (int)(row % N);
    int half = (int)(row / N);
    float ci = half ? ci_dis[n] : ci_drug[n];
    out[idx] = out[idx] * ci + bias[o];
}

// ---------------------------------------------------------------------------
extern "C" void kernel_launch(void* const* d_in, const int* in_sizes, int n_in,
                              void* d_out, int out_size) {
    const int*   drug_feat = (const int*)d_in[0];
    const int*   dis_feat  = (const int*)d_in[1];
    const int*   src       = (const int*)d_in[2];
    const int*   dst       = (const int*)d_in[3];
    const float* cj_drug   = (const float*)d_in[4];
    const float* ci_drug   = (const float*)d_in[5];
    const float* cj_dis    = (const float*)d_in[6];
    const float* ci_dis    = (const float*)d_in[7];
    const float* att       = (const float*)d_in[8];
    const float* basis     = (const float*)d_in[9];
    const float* fc_w      = (const float*)d_in[10];
    const float* fc_b      = (const float*)d_in[11];
    float* out = (float*)d_out;

    const int N   = in_sizes[4];
    const int E   = in_sizes[2] / RR;
    const int OUT = in_sizes[11];
    const int MU  = in_sizes[10] / (OUT * 3 * RR);
    const int IN  = in_sizes[9] / (BU * MU);
    const int nbins = NPART * N;

    cudaMemsetAsync(d_out, 0, (size_t)out_size * sizeof(float), 0);

    // Weight precompute
    {
        int total = RR * IN * MU;
        k_W<<<(total + 255) / 256, 256>>>(att, basis, IN, MU);
    }
    k_P<<<RR * 3 * IN, OUT>>>(fc_w, IN, MU, OUT);

    // CSR build over all 10 partitions
    k_zero<<<(nbins + 255) / 256, 256>>>(nbins);
    {
        int tot = NPART * E;
        k_hist<<<(tot + 255) / 256, 256>>>(src, dst, E, N);
    }
    {
        int nb = (nbins + 511) / 512;
        k_scan1<<<nb, 512>>>(nbins);
        k_scan2<<<1, 1024>>>(nb);
        k_scan3<<<(nbins + 255) / 256, 256>>>(nbins);
    }
    {
        int tot = NPART * E;
        k_place<<<(tot + 255) / 256, 256>>>(src, dst, E, N);
    }

    const int mBlocks = (int)(((long long)N * 32 + 255) / 256);
    const int gBlocks = (int)(((long long)2 * N * 32 + 255) / 256);
    float* out_drug = out;
    float* out_dis  = out + (size_t)N * OUT;

    // dir 0: drug -> dis (bins keyed by dst), messages from drug nodes
    for (int r = 0; r < RR; r++) {
        k_m<<<mBlocks, 256>>>(drug_feat, cj_drug, r, N, IN, OUT);
        k_gather<<<gBlocks, 256>>>(r, out_dis, N);
    }
    // dir 1: dis -> drug (bins keyed by src), messages from dis nodes
    for (int r = 0; r < RR; r++) {
        k_m<<<mBlocks, 256>>>(dis_feat, cj_dis, r, N, IN, OUT);
        k_gather<<<gBlocks, 256>>>(RR + r, out_drug, N);
    }

    {
        long long total = 2LL * N * OUT;
        k_fin<<<(int)((total + 255) / 256), 256>>>(out, ci_drug, ci_dis, fc_b, N, OUT);
    }
}

// round 3
// speedup vs baseline: 2.3925x; 1.6210x over previous
#include <cuda_runtime.h>
#include <cuda_fp16.h>
#include <cstdint>

#define RR 5
#define BU 4
#define MAX_IN 1024
#define MAX_MU 64
#define MAX_OUT 256
#define MAX_N 50000
#define MAX_E 500000
#define NPART (2 * RR)
#define NBINS (NPART * MAX_N)

// Static scratch
__device__ float  g_W[RR * MAX_IN * MAX_MU];               // 1.3 MB
__device__ float  g_P[RR * 3 * MAX_IN * MAX_OUT];          // 15.7 MB
__device__ __half g_mh[(size_t)RR * MAX_N * MAX_OUT];      // 128 MB fp16 messages (5 ratings)
__device__ int    g_cnt[NBINS];
__device__ int    g_off[NBINS + 1];
__device__ int    g_cur[NBINS];
__device__ int    g_pay[NPART * MAX_E];
__device__ int    g_bsum[1024];

// ---------------------------------------------------------------------------
__global__ void k_W(const float* __restrict__ att, const float* __restrict__ basis,
                    int IN, int MU) {
    int idx = blockIdx.x * blockDim.x + threadIdx.x;
    int total = RR * IN * MU;
    if (idx >= total) return;
    int m = idx % MU;
    int i = (idx / MU) % IN;
    int r = idx / (MU * IN);
    float acc = 0.f;
#pragma unroll
    for (int b = 0; b < BU; b++)
        acc += att[r * BU + b] * basis[(b * IN + i) * MU + m];
    g_W[idx] = acc;
}

__global__ void k_P(const float* __restrict__ fc_w, int IN, int MU, int OUT) {
    int o  = threadIdx.x;
    int i  = blockIdx.x % IN;
    int rk = blockIdx.x / IN;
    const float* wrow = g_W + ((size_t)(rk / 3) * IN + i) * MU;
    const float* fcb  = fc_w + (size_t)(rk * MU) * OUT + o;
    float acc = 0.f;
#pragma unroll 8
    for (int m = 0; m < MU; m++)
        acc = fmaf(wrow[m], fcb[(size_t)m * OUT], acc);
    g_P[((size_t)rk * IN + i) * OUT + o] = acc;
}

// --------------------------- CSR build -------------------------------------
__global__ void k_zero(int n) {
    int i = blockIdx.x * blockDim.x + threadIdx.x;
    if (i < n) g_cnt[i] = 0;
}

__global__ void k_hist(const int* __restrict__ src, const int* __restrict__ dst,
                       int E, int N) {
    int idx = blockIdx.x * blockDim.x + threadIdx.x;
    if (idx >= NPART * E) return;
    int e = idx % E;
    int p = idx / E;
    int r = p % RR;
    int key = (p < RR) ? dst[(size_t)r * E + e] : src[(size_t)r * E + e];
    atomicAdd(&g_cnt[p * N + key], 1);
}

__global__ void k_scan1(int n) {
    __shared__ int sh[512];
    int tid = threadIdx.x;
    int i = blockIdx.x * 512 + tid;
    int v = (i < n) ? g_cnt[i] : 0;
    sh[tid] = v;
    __syncthreads();
#pragma unroll
    for (int ofs = 1; ofs < 512; ofs <<= 1) {
        int t = (tid >= ofs) ? sh[tid - ofs] : 0;
        __syncthreads();
        sh[tid] += t;
        __syncthreads();
    }
    if (i < n) g_off[i] = sh[tid];
    if (tid == 511) g_bsum[blockIdx.x] = sh[511];
}

__global__ void k_scan2(int nb) {
    __shared__ int sh[1024];
    int tid = threadIdx.x;
    sh[tid] = (tid < nb) ? g_bsum[tid] : 0;
    __syncthreads();
#pragma unroll
    for (int ofs = 1; ofs < 1024; ofs <<= 1) {
        int t = (tid >= ofs) ? sh[tid - ofs] : 0;
        __syncthreads();
        sh[tid] += t;
        __syncthreads();
    }
    if (tid < nb) g_bsum[tid] = sh[tid];
}

__global__ void k_scan3(int n) {
    int i = blockIdx.x * blockDim.x + threadIdx.x;
    if (i >= n) return;
    int blk = i >> 9;
    int excl = g_off[i] - g_cnt[i] + (blk ? g_bsum[blk - 1] : 0);
    g_off[i] = excl;
    g_cur[i] = excl;
    if (i == n - 1) g_off[n] = excl + g_cnt[i];
}

__global__ void k_place(const int* __restrict__ src, const int* __restrict__ dst,
                        int E, int N) {
    int idx = blockIdx.x * blockDim.x + threadIdx.x;
    if (idx >= NPART * E) return;
    int e = idx % E;
    int p = idx / E;
    int r = p % RR;
    int key, pay;
    if (p < RR) { key = dst[(size_t)r * E + e]; pay = src[(size_t)r * E + e]; }
    else        { key = src[(size_t)r * E + e]; pay = dst[(size_t)r * E + e]; }
    int pos = atomicAdd(&g_cur[p * N + key], 1);
    g_pay[pos] = pay;
}

// ---------------------------------------------------------------------------
// Messages for ALL 5 ratings of one node type. One warp per (node, rating).
// Lane owns 8 columns; writes 16B of fp16 per lane.
__global__ void k_m_all(const int* __restrict__ feat, const float* __restrict__ cj,
                        int N, int IN) {
    int gw = (blockIdx.x * blockDim.x + threadIdx.x) >> 5;
    int lane = threadIdx.x & 31;
    if (gw >= N * RR) return;
    int r = gw % RR;
    int n = gw / RR;
    int f0 = feat[n * 3 + 0];
    int f1 = feat[n * 3 + 1];
    int f2 = feat[n * 3 + 2];
    float c = cj[n];
    int base = lane * 8;                       // column base (of 256)
    const float4* p0 = (const float4*)(g_P + ((size_t)(r * 3 + 0) * IN + f0) * 256 + base);
    const float4* p1 = (const float4*)(g_P + ((size_t)(r * 3 + 1) * IN + f1) * 256 + base);
    const float4* p2 = (const float4*)(g_P + ((size_t)(r * 3 + 2) * IN + f2) * 256 + base);
    float4 a0 = p0[0], a1 = p0[1];
    float4 b0 = p1[0], b1 = p1[1];
    float4 d0 = p2[0], d1 = p2[1];
    float v0 = c * (a0.x + b0.x + d0.x);
    float v1 = c * (a0.y + b0.y + d0.y);
    float v2 = c * (a0.z + b0.z + d0.z);
    float v3 = c * (a0.w + b0.w + d0.w);
    float v4 = c * (a1.x + b1.x + d1.x);
    float v5 = c * (a1.y + b1.y + d1.y);
    float v6 = c * (a1.z + b1.z + d1.z);
    float v7 = c * (a1.w + b1.w + d1.w);
    __half2 h0 = __floats2half2_rn(v0, v1);
    __half2 h1 = __floats2half2_rn(v2, v3);
    __half2 h2 = __floats2half2_rn(v4, v5);
    __half2 h3 = __floats2half2_rn(v6, v7);
    uint4 pack;
    pack.x = *(const unsigned int*)&h0;
    pack.y = *(const unsigned int*)&h1;
    pack.z = *(const unsigned int*)&h2;
    pack.w = *(const unsigned int*)&h3;
    uint4* dstp = (uint4*)(g_mh + ((size_t)r * N + n) * 256 + base);
    *dstp = pack;
}

// ---------------------------------------------------------------------------
// Fused gather over all 5 ratings of one direction, epilogue = *ci + bias.
// One warp per destination node; lane owns 8 columns (fp32 accumulators).
__global__ void k_gather(int dir, const float* __restrict__ ci,
                         const float* __restrict__ bias,
                         float* __restrict__ outh, int N) {
    int n = (blockIdx.x * blockDim.x + threadIdx.x) >> 5;
    int lane = threadIdx.x & 31;
    if (n >= N) return;
    int base = lane * 8;
    float acc0 = 0.f, acc1 = 0.f, acc2 = 0.f, acc3 = 0.f;
    float acc4 = 0.f, acc5 = 0.f, acc6 = 0.f, acc7 = 0.f;

#pragma unroll
    for (int r = 0; r < RR; r++) {
        int p = dir * RR + r;
        int s0 = g_off[p * MAX_N + n];       // bins contiguous; [p*N+n, p*N+n+1)
        int s1 = g_off[p * MAX_N + n + 1];
        const __half* mb = g_mh + (size_t)r * N * 256;
        int j = s0;
        for (; j + 1 < s1; j += 2) {
            int sa = g_pay[j];
            int sb = g_pay[j + 1];
            uint4 va = *(const uint4*)(mb + (size_t)sa * 256 + base);
            uint4 vb = *(const uint4*)(mb + (size_t)sb * 256 + base);
            float2 fa0 = __half22float2(*(const __half2*)&va.x);
            float2 fa1 = __half22float2(*(const __half2*)&va.y);
            float2 fa2 = __half22float2(*(const __half2*)&va.z);
            float2 fa3 = __half22float2(*(const __half2*)&va.w);
            acc0 += fa0.x; acc1 += fa0.y; acc2 += fa1.x; acc3 += fa1.y;
            acc4 += fa2.x; acc5 += fa2.y; acc6 += fa3.x; acc7 += fa3.y;
            float2 fb0 = __half22float2(*(const __half2*)&vb.x);
            float2 fb1 = __half22float2(*(const __half2*)&vb.y);
            float2 fb2 = __half22float2(*(const __half2*)&vb.z);
            float2 fb3 = __half22float2(*(const __half2*)&vb.w);
            acc0 += fb0.x; acc1 += fb0.y; acc2 += fb1.x; acc3 += fb1.y;
            acc4 += fb2.x; acc5 += fb2.y; acc6 += fb3.x; acc7 += fb3.y;
        }
        if (j < s1) {
            int sa = g_pay[j];
            uint4 va = *(const uint4*)(mb + (size_t)sa * 256 + base);
            float2 fa0 = __half22float2(*(const __half2*)&va.x);
            float2 fa1 = __half22float2(*(const __half2*)&va.y);
            float2 fa2 = __half22float2(*(const __half2*)&va.z);
            float2 fa3 = __half22float2(*(const __half2*)&va.w);
            acc0 += fa0.x; acc1 += fa0.y; acc2 += fa1.x; acc3 += fa1.y;
            acc4 += fa2.x; acc5 += fa2.y; acc6 += fa3.x; acc7 += fa3.y;
        }
    }

    float c = ci[n];
    const float4* bb = (const float4*)(bias + base);
    float4 bv0 = bb[0], bv1 = bb[1];
    float4 o0, o1;
    o0.x = acc0 * c + bv0.x;  o0.y = acc1 * c + bv0.y;
    o0.z = acc2 * c + bv0.z;  o0.w = acc3 * c + bv0.w;
    o1.x = acc4 * c + bv1.x;  o1.y = acc5 * c + bv1.y;
    o1.z = acc6 * c + bv1.z;  o1.w = acc7 * c + bv1.w;
    float4* op = (float4*)(outh + (size_t)n * 256 + base);
    op[0] = o0;
    op[1] = o1;
}

// ---------------------------------------------------------------------------
extern "C" void kernel_launch(void* const* d_in, const int* in_sizes, int n_in,
                              void* d_out, int out_size) {
    const int*   drug_feat = (const int*)d_in[0];
    const int*   dis_feat  = (const int*)d_in[1];
    const int*   src       = (const int*)d_in[2];
    const int*   dst       = (const int*)d_in[3];
    const float* cj_drug   = (const float*)d_in[4];
    const float* ci_drug   = (const float*)d_in[5];
    const float* cj_dis    = (const float*)d_in[6];
    const float* ci_dis    = (const float*)d_in[7];
    const float* att       = (const float*)d_in[8];
    const float* basis     = (const float*)d_in[9];
    const float* fc_w      = (const float*)d_in[10];
    const float* fc_b      = (const float*)d_in[11];
    float* out = (float*)d_out;

    const int N   = in_sizes[4];
    const int E   = in_sizes[2] / RR;
    const int OUT = in_sizes[11];
    const int MU  = in_sizes[10] / (OUT * 3 * RR);
    const int IN  = in_sizes[9] / (BU * MU);
    const int nbins = NPART * N;

    // Weight precompute
    {
        int total = RR * IN * MU;
        k_W<<<(total + 255) / 256, 256>>>(att, basis, IN, MU);
    }
    k_P<<<RR * 3 * IN, OUT>>>(fc_w, IN, MU, OUT);

    // CSR build (10 partitions)
    k_zero<<<(nbins + 255) / 256, 256>>>(nbins);
    {
        int tot = NPART * E;
        k_hist<<<(tot + 255) / 256, 256>>>(src, dst, E, N);
    }
    {
        int nb = (nbins + 511) / 512;
        k_scan1<<<nb, 512>>>(nbins);
        k_scan2<<<1, 1024>>>(nb);
        k_scan3<<<(nbins + 255) / 256, 256>>>(nbins);
    }
    {
        int tot = NPART * E;
        k_place<<<(tot + 255) / 256, 256>>>(src, dst, E, N);
    }

    const int mBlocks = (int)(((long long)N * RR * 32 + 255) / 256);
    const int gBlocks = (int)(((long long)N * 32 + 255) / 256);
    float* out_drug = out;
    float* out_dis  = out + (size_t)N * OUT;

    // dir 0: drug -> dis
    k_m_all<<<mBlocks, 256>>>(drug_feat, cj_drug, N, IN);
    k_gather<<<gBlocks, 256>>>(0, ci_dis, fc_b, out_dis, N);

    // dir 1: dis -> drug
    k_m_all<<<mBlocks, 256>>>(dis_feat, cj_dis, N, IN);
    k_gather<<<gBlocks, 256>>>(1, ci_drug, fc_b, out_drug, N);
}

// round 4
// speedup vs baseline: 2.4268x; 1.0143x over previous
#include <cuda_runtime.h>
#include <cuda_fp16.h>
#include <cstdint>

#define RR 5
#define BU 4
#define MAX_IN 1024
#define MAX_MU 64
#define MAX_OUT 256
#define MAX_N 50000
#define MAX_E 500000
#define NPART (2 * RR)
#define NBINS (NPART * MAX_N)

// Static scratch
__device__ float  g_P[RR * 3 * MAX_IN * MAX_OUT];               // 15.7 MB
__device__ __half g_mh[2][(size_t)RR * MAX_N * MAX_OUT];        // 2 x 128 MB fp16 messages
__device__ int    g_cnt[NBINS];
__device__ int    g_off[NBINS + 1];
__device__ int    g_cur[NBINS];
__device__ int    g_pay[NPART * MAX_E];
__device__ int    g_bsum[1024];

// ---------------------------------------------------------------------------
// P[rk][i][o] = sum_m (sum_b att[r,b]*basis[b,i,m]) * fc_w[(rk*MU+m)*OUT+o]
// k_W fused in: W row recomputed per block (cheap, basis rows are L1-broadcast).
__global__ void k_P(const float* __restrict__ att, const float* __restrict__ basis,
                    const float* __restrict__ fc_w, int IN, int MU, int OUT) {
    __shared__ float wrow[MAX_MU];
    int o  = threadIdx.x;
    int i  = blockIdx.x % IN;
    int rk = blockIdx.x / IN;
    int r  = rk / 3;
    // threads 0..MU-1 build W[r][i][:]
    if (o < MU) {
        float acc = 0.f;
#pragma unroll
        for (int b = 0; b < BU; b++)
            acc += att[r * BU + b] * basis[((size_t)b * IN + i) * MU + o];
        wrow[o] = acc;
    }
    __syncthreads();
    const float* fcb = fc_w + (size_t)(rk * MU) * OUT + o;
    float acc = 0.f;
#pragma unroll 8
    for (int m = 0; m < MU; m++)
        acc = fmaf(wrow[m], fcb[(size_t)m * OUT], acc);
    g_P[((size_t)rk * IN + i) * OUT + o] = acc;
}

// --------------------------- CSR build -------------------------------------
__global__ void k_hist(const int* __restrict__ src, const int* __restrict__ dst,
                       int E, int N) {
    int idx = blockIdx.x * blockDim.x + threadIdx.x;
    if (idx >= NPART * E) return;
    int e = idx % E;
    int p = idx / E;
    int r = p % RR;
    int key = (p < RR) ? dst[(size_t)r * E + e] : src[(size_t)r * E + e];
    atomicAdd(&g_cnt[p * N + key], 1);
}

__global__ void k_scan1(int n) {
    __shared__ int sh[512];
    int tid = threadIdx.x;
    int i = blockIdx.x * 512 + tid;
    int v = (i < n) ? g_cnt[i] : 0;
    sh[tid] = v;
    __syncthreads();
#pragma unroll
    for (int ofs = 1; ofs < 512; ofs <<= 1) {
        int t = (tid >= ofs) ? sh[tid - ofs] : 0;
        __syncthreads();
        sh[tid] += t;
        __syncthreads();
    }
    if (i < n) g_off[i] = sh[tid];
    if (tid == 511) g_bsum[blockIdx.x] = sh[511];
}

__global__ void k_scan2(int nb) {
    __shared__ int sh[1024];
    int tid = threadIdx.x;
    sh[tid] = (tid < nb) ? g_bsum[tid] : 0;
    __syncthreads();
#pragma unroll
    for (int ofs = 1; ofs < 1024; ofs <<= 1) {
        int t = (tid >= ofs) ? sh[tid - ofs] : 0;
        __syncthreads();
        sh[tid] += t;
        __syncthreads();
    }
    if (tid < nb) g_bsum[tid] = sh[tid];
}

__global__ void k_scan3(int n) {
    int i = blockIdx.x * blockDim.x + threadIdx.x;
    if (i >= n) return;
    int blk = i >> 9;
    int excl = g_off[i] - g_cnt[i] + (blk ? g_bsum[blk - 1] : 0);
    g_off[i] = excl;
    g_cur[i] = excl;
    if (i == n - 1) g_off[n] = excl + g_cnt[i];
}

__global__ void k_place(const int* __restrict__ src, const int* __restrict__ dst,
                        int E, int N) {
    int idx = blockIdx.x * blockDim.x + threadIdx.x;
    if (idx >= NPART * E) return;
    int e = idx % E;
    int p = idx / E;
    int r = p % RR;
    int key, pay;
    if (p < RR) { key = dst[(size_t)r * E + e]; pay = src[(size_t)r * E + e]; }
    else        { key = src[(size_t)r * E + e]; pay = dst[(size_t)r * E + e]; }
    int pos = atomicAdd(&g_cur[p * N + key], 1);
    g_pay[pos] = pay;
}

// ---------------------------------------------------------------------------
// Messages for ALL 5 ratings of one node type. One warp per (node, rating).
__global__ void k_m_all(const int* __restrict__ feat, const float* __restrict__ cj,
                        int N, int IN, int buf) {
    int gw = (blockIdx.x * blockDim.x + threadIdx.x) >> 5;
    int lane = threadIdx.x & 31;
    if (gw >= N * RR) return;
    int r = gw % RR;
    int n = gw / RR;
    int f0 = feat[n * 3 + 0];
    int f1 = feat[n * 3 + 1];
    int f2 = feat[n * 3 + 2];
    float c = cj[n];
    int base = lane * 8;
    const float4* p0 = (const float4*)(g_P + ((size_t)(r * 3 + 0) * IN + f0) * 256 + base);
    const float4* p1 = (const float4*)(g_P + ((size_t)(r * 3 + 1) * IN + f1) * 256 + base);
    const float4* p2 = (const float4*)(g_P + ((size_t)(r * 3 + 2) * IN + f2) * 256 + base);
    float4 a0 = p0[0], a1 = p0[1];
    float4 b0 = p1[0], b1 = p1[1];
    float4 d0 = p2[0], d1 = p2[1];
    __half2 h0 = __floats2half2_rn(c * (a0.x + b0.x + d0.x), c * (a0.y + b0.y + d0.y));
    __half2 h1 = __floats2half2_rn(c * (a0.z + b0.z + d0.z), c * (a0.w + b0.w + d0.w));
    __half2 h2 = __floats2half2_rn(c * (a1.x + b1.x + d1.x), c * (a1.y + b1.y + d1.y));
    __half2 h3 = __floats2half2_rn(c * (a1.z + b1.z + d1.z), c * (a1.w + b1.w + d1.w));
    uint4 pack;
    pack.x = *(const unsigned int*)&h0;
    pack.y = *(const unsigned int*)&h1;
    pack.z = *(const unsigned int*)&h2;
    pack.w = *(const unsigned int*)&h3;
    uint4* dstp = (uint4*)(g_mh[buf] + ((size_t)r * N + n) * 256 + base);
    *dstp = pack;
}

// ---------------------------------------------------------------------------
// Fused gather over 5 ratings of one direction, ONE column half (128 cols).
// One warp per node; lane owns 4 fp16 cols (uint2 load). MLP=4 inner loop.
__global__ void k_gather(int dir, int half, const float* __restrict__ ci,
                         const float* __restrict__ bias,
                         float* __restrict__ outh, int N) {
    int n = (blockIdx.x * blockDim.x + threadIdx.x) >> 5;
    int lane = threadIdx.x & 31;
    if (n >= N) return;
    int base = half * 128 + lane * 4;             // fp16 column base
    int buf = dir;                                 // dir0 gathers drug buf(0), dir1 dis buf(1)
    float acc0 = 0.f, acc1 = 0.f, acc2 = 0.f, acc3 = 0.f;

#pragma unroll
    for (int r = 0; r < RR; r++) {
        int p = dir * RR + r;
        int s0 = g_off[p * MAX_N + n];
        int s1 = g_off[p * MAX_N + n + 1];
        const __half* mb = g_mh[buf] + (size_t)r * N * 256;
        int j = s0;
        for (; j + 3 < s1; j += 4) {
            int sa = g_pay[j + 0];
            int sb = g_pay[j + 1];
            int sc = g_pay[j + 2];
            int sd = g_pay[j + 3];
            uint2 va = *(const uint2*)(mb + (size_t)sa * 256 + base);
            uint2 vb = *(const uint2*)(mb + (size_t)sb * 256 + base);
            uint2 vc = *(const uint2*)(mb + (size_t)sc * 256 + base);
            uint2 vd = *(const uint2*)(mb + (size_t)sd * 256 + base);
            float2 f;
            f = __half22float2(*(const __half2*)&va.x); acc0 += f.x; acc1 += f.y;
            f = __half22float2(*(const __half2*)&va.y); acc2 += f.x; acc3 += f.y;
            f = __half22float2(*(const __half2*)&vb.x); acc0 += f.x; acc1 += f.y;
            f = __half22float2(*(const __half2*)&vb.y); acc2 += f.x; acc3 += f.y;
            f = __half22float2(*(const __half2*)&vc.x); acc0 += f.x; acc1 += f.y;
            f = __half22float2(*(const __half2*)&vc.y); acc2 += f.x; acc3 += f.y;
            f = __half22float2(*(const __half2*)&vd.x); acc0 += f.x; acc1 += f.y;
            f = __half22float2(*(const __half2*)&vd.y); acc2 += f.x; acc3 += f.y;
        }
        for (; j < s1; j++) {
            int sa = g_pay[j];
            uint2 va = *(const uint2*)(mb + (size_t)sa * 256 + base);
            float2 f;
            f = __half22float2(*(const __half2*)&va.x); acc0 += f.x; acc1 += f.y;
            f = __half22float2(*(const __half2*)&va.y); acc2 += f.x; acc3 += f.y;
        }
    }

    float c = ci[n];
    const float4* bb = (const float4*)(bias + base);
    float4 bv = bb[0];
    float4 o;
    o.x = acc0 * c + bv.x;
    o.y = acc1 * c + bv.y;
    o.z = acc2 * c + bv.z;
    o.w = acc3 * c + bv.w;
    *((float4*)(outh + (size_t)n * 256 + base)) = o;
}

// ---------------------------------------------------------------------------
extern "C" void kernel_launch(void* const* d_in, const int* in_sizes, int n_in,
                              void* d_out, int out_size) {
    const int*   drug_feat = (const int*)d_in[0];
    const int*   dis_feat  = (const int*)d_in[1];
    const int*   src       = (const int*)d_in[2];
    const int*   dst       = (const int*)d_in[3];
    const float* cj_drug   = (const float*)d_in[4];
    const float* ci_drug   = (const float*)d_in[5];
    const float* cj_dis    = (const float*)d_in[6];
    const float* ci_dis    = (const float*)d_in[7];
    const float* att       = (const float*)d_in[8];
    const float* basis     = (const float*)d_in[9];
    const float* fc_w      = (const float*)d_in[10];
    const float* fc_b      = (const float*)d_in[11];
    float* out = (float*)d_out;

    const int N   = in_sizes[4];
    const int E   = in_sizes[2] / RR;
    const int OUT = in_sizes[11];
    const int MU  = in_sizes[10] / (OUT * 3 * RR);
    const int IN  = in_sizes[9] / (BU * MU);
    const int nbins = NPART * N;

    // CSR build (independent of weights)
    void* cntPtr = nullptr;
    cudaGetSymbolAddress(&cntPtr, g_cnt);
    cudaMemsetAsync(cntPtr, 0, (size_t)nbins * sizeof(int), 0);
    {
        int tot = NPART * E;
        k_hist<<<(tot + 255) / 256, 256>>>(src, dst, E, N);
    }
    {
        int nb = (nbins + 511) / 512;
        k_scan1<<<nb, 512>>>(nbins);
        k_scan2<<<1, 1024>>>(nb);
        k_scan3<<<(nbins + 255) / 256, 256>>>(nbins);
    }
    {
        int tot = NPART * E;
        k_place<<<(tot + 255) / 256, 256>>>(src, dst, E, N);
    }

    // Weights (k_W fused into k_P)
    k_P<<<RR * 3 * IN, OUT>>>(att, basis, fc_w, IN, MU, OUT);

    const int mBlocks = (int)(((long long)N * RR * 32 + 255) / 256);
    const int gBlocks = (int)(((long long)N * 32 + 255) / 256);
    float* out_drug = out;
    float* out_dis  = out + (size_t)N * OUT;

    // Messages: drug -> buf0, dis -> buf1
    k_m_all<<<mBlocks, 256>>>(drug_feat, cj_drug, N, IN, 0);
    k_m_all<<<mBlocks, 256>>>(dis_feat, cj_dis, N, IN, 1);

    // dir 0 (drug->dis, reads buf0), per column half
    k_gather<<<gBlocks, 256>>>(0, 0, ci_dis, fc_b, out_dis, N);
    k_gather<<<gBlocks, 256>>>(0, 1, ci_dis, fc_b, out_dis, N);
    // dir 1 (dis->drug, reads buf1)
    k_gather<<<gBlocks, 256>>>(1, 0, ci_drug, fc_b, out_drug, N);
    k_gather<<<gBlocks, 256>>>(1, 1, ci_drug, fc_b, out_drug, N);
}

// round 5
// speedup vs baseline: 2.5613x; 1.0554x over previous
#include <cuda_runtime.h>
#include <cuda_fp16.h>
#include <cstdint>

#define RR 5
#define BU 4
#define MAX_IN 1024
#define MAX_MU 64
#define MAX_OUT 256
#define MAX_N 50000
#define MAX_E 500000
#define NPART (2 * RR)
#define NBINS (NPART * MAX_N)

// Static scratch
__device__ __half g_Ph[RR * 3 * MAX_IN * MAX_OUT];              // 7.9 MB fp16 P
__device__ __half g_mh[2][(size_t)RR * MAX_N * MAX_OUT];        // 2 x 128 MB fp16 messages
__device__ int    g_cnt[NBINS];
__device__ int    g_off[NBINS];                                 // excl offsets -> advanced to END by k_place
__device__ int    g_pay[NPART * MAX_E];
__device__ int    g_bsum[1024];

// ---------------------------------------------------------------------------
// P[rk][i][o] = sum_m (sum_b att[r,b]*basis[b,i,m]) * fc_w[(rk*MU+m)*OUT+o], fp16 out
__global__ void k_P(const float* __restrict__ att, const float* __restrict__ basis,
                    const float* __restrict__ fc_w, int IN, int MU, int OUT) {
    __shared__ float wrow[MAX_MU];
    int o  = threadIdx.x;
    int i  = blockIdx.x % IN;
    int rk = blockIdx.x / IN;
    int r  = rk / 3;
    if (o < MU) {
        float acc = 0.f;
#pragma unroll
        for (int b = 0; b < BU; b++)
            acc += att[r * BU + b] * basis[((size_t)b * IN + i) * MU + o];
        wrow[o] = acc;
    }
    __syncthreads();
    const float* fcb = fc_w + (size_t)(rk * MU) * OUT + o;
    float acc = 0.f;
#pragma unroll 8
    for (int m = 0; m < MU; m++)
        acc = fmaf(wrow[m], fcb[(size_t)m * OUT], acc);
    g_Ph[((size_t)rk * IN + i) * OUT + o] = __float2half_rn(acc);
}

// --------------------------- CSR build -------------------------------------
__global__ void k_hist(const int* __restrict__ src, const int* __restrict__ dst,
                       int E, int N) {
    int idx = blockIdx.x * blockDim.x + threadIdx.x;
    if (idx >= NPART * E) return;
    int e = idx % E;
    int p = idx / E;
    int r = p % RR;
    int key = (p < RR) ? dst[(size_t)r * E + e] : src[(size_t)r * E + e];
    atomicAdd(&g_cnt[p * N + key], 1);
}

__global__ void k_scan1(int n) {
    __shared__ int sh[512];
    int tid = threadIdx.x;
    int i = blockIdx.x * 512 + tid;
    int v = (i < n) ? g_cnt[i] : 0;
    sh[tid] = v;
    __syncthreads();
#pragma unroll
    for (int ofs = 1; ofs < 512; ofs <<= 1) {
        int t = (tid >= ofs) ? sh[tid - ofs] : 0;
        __syncthreads();
        sh[tid] += t;
        __syncthreads();
    }
    if (i < n) g_off[i] = sh[tid];           // inclusive, temp
    if (tid == 511) g_bsum[blockIdx.x] = sh[511];
}

__global__ void k_scan2(int nb) {
    __shared__ int sh[1024];
    int tid = threadIdx.x;
    sh[tid] = (tid < nb) ? g_bsum[tid] : 0;
    __syncthreads();
#pragma unroll
    for (int ofs = 1; ofs < 1024; ofs <<= 1) {
        int t = (tid >= ofs) ? sh[tid - ofs] : 0;
        __syncthreads();
        sh[tid] += t;
        __syncthreads();
    }
    if (tid < nb) g_bsum[tid] = sh[tid];
}

// finalize: g_off[i] = exclusive offset
__global__ void k_scan3(int n) {
    int i = blockIdx.x * blockDim.x + threadIdx.x;
    if (i >= n) return;
    int blk = i >> 9;
    g_off[i] = g_off[i] - g_cnt[i] + (blk ? g_bsum[blk - 1] : 0);
}

// place: atomically advance g_off; afterwards g_off[i] == END of bin i
__global__ void k_place(const int* __restrict__ src, const int* __restrict__ dst,
                        int E, int N) {
    int idx = blockIdx.x * blockDim.x + threadIdx.x;
    if (idx >= NPART * E) return;
    int e = idx % E;
    int p = idx / E;
    int r = p % RR;
    int key, pay;
    if (p < RR) { key = dst[(size_t)r * E + e]; pay = src[(size_t)r * E + e]; }
    else        { key = src[(size_t)r * E + e]; pay = dst[(size_t)r * E + e]; }
    int pos = atomicAdd(&g_off[p * N + key], 1);
    g_pay[pos] = pay;
}

// ---------------------------------------------------------------------------
// Messages for both node types, all ratings. One warp per (type, node, rating).
__global__ void k_m_all(const int* __restrict__ drug_feat, const int* __restrict__ dis_feat,
                        const float* __restrict__ cj_drug, const float* __restrict__ cj_dis,
                        int N, int IN) {
    int gw = (blockIdx.x * blockDim.x + threadIdx.x) >> 5;
    int lane = threadIdx.x & 31;
    int tot = N * RR;
    if (gw >= 2 * tot) return;
    int type = gw >= tot;
    int local = gw - type * tot;
    int r = local % RR;
    int n = local / RR;
    const int* feat = type ? dis_feat : drug_feat;
    const float* cj = type ? cj_dis : cj_drug;
    int f0 = feat[n * 3 + 0];
    int f1 = feat[n * 3 + 1];
    int f2 = feat[n * 3 + 2];
    float c = cj[n];
    int base = lane * 8;
    const uint4* p0 = (const uint4*)(g_Ph + ((size_t)(r * 3 + 0) * IN + f0) * 256 + base);
    const uint4* p1 = (const uint4*)(g_Ph + ((size_t)(r * 3 + 1) * IN + f1) * 256 + base);
    const uint4* p2 = (const uint4*)(g_Ph + ((size_t)(r * 3 + 2) * IN + f2) * 256 + base);
    uint4 ua = *p0, ub = *p1, ud = *p2;
    uint4 pack;
    const unsigned int* pa = &ua.x;
    const unsigned int* pb = &ub.x;
    const unsigned int* pd = &ud.x;
    unsigned int* po = &pack.x;
#pragma unroll
    for (int q = 0; q < 4; q++) {
        float2 fa = __half22float2(*(const __half2*)&pa[q]);
        float2 fb = __half22float2(*(const __half2*)&pb[q]);
        float2 fd = __half22float2(*(const __half2*)&pd[q]);
        __half2 h = __floats2half2_rn(c * (fa.x + fb.x + fd.x), c * (fa.y + fb.y + fd.y));
        po[q] = *(const unsigned int*)&h;
    }
    uint4* dstp = (uint4*)(g_mh[type] + ((size_t)r * N + n) * 256 + base);
    *dstp = pack;
}

// ---------------------------------------------------------------------------
// Fused gather over 5 ratings of one direction, full 256 cols.
// One warp per node; lane owns 8 fp16 cols (uint4 load). 4 edges in flight.
__global__ void k_gather(int dir, const float* __restrict__ ci,
                         const float* __restrict__ bias,
                         float* __restrict__ outh, int N) {
    int n = (blockIdx.x * blockDim.x + threadIdx.x) >> 5;
    int lane = threadIdx.x & 31;
    if (n >= N) return;
    int base = lane * 8;
    float acc0 = 0.f, acc1 = 0.f, acc2 = 0.f, acc3 = 0.f;
    float acc4 = 0.f, acc5 = 0.f, acc6 = 0.f, acc7 = 0.f;

#pragma unroll
    for (int r = 0; r < RR; r++) {
        int bin = (dir * RR + r) * N + n;
        int s1 = g_off[bin];                 // end (post-place)
        int s0 = s1 - g_cnt[bin];
        const __half* mb = g_mh[dir] + (size_t)r * N * 256;
        int j = s0;
        for (; j + 3 < s1; j += 4) {
            int sa = g_pay[j + 0];
            int sb = g_pay[j + 1];
            int sc = g_pay[j + 2];
            int sd = g_pay[j + 3];
            uint4 va = *(const uint4*)(mb + (size_t)sa * 256 + base);
            uint4 vb = *(const uint4*)(mb + (size_t)sb * 256 + base);
            uint4 vc = *(const uint4*)(mb + (size_t)sc * 256 + base);
            uint4 vd = *(const uint4*)(mb + (size_t)sd * 256 + base);
            float2 f;
            f = __half22float2(*(const __half2*)&va.x); acc0 += f.x; acc1 += f.y;
            f = __half22float2(*(const __half2*)&va.y); acc2 += f.x; acc3 += f.y;
            f = __half22float2(*(const __half2*)&va.z); acc4 += f.x; acc5 += f.y;
            f = __half22float2(*(const __half2*)&va.w); acc6 += f.x; acc7 += f.y;
            f = __half22float2(*(const __half2*)&vb.x); acc0 += f.x; acc1 += f.y;
            f = __half22float2(*(const __half2*)&vb.y); acc2 += f.x; acc3 += f.y;
            f = __half22float2(*(const __half2*)&vb.z); acc4 += f.x; acc5 += f.y;
            f = __half22float2(*(const __half2*)&vb.w); acc6 += f.x; acc7 += f.y;
            f = __half22float2(*(const __half2*)&vc.x); acc0 += f.x; acc1 += f.y;
            f = __half22float2(*(const __half2*)&vc.y); acc2 += f.x; acc3 += f.y;
            f = __half22float2(*(const __half2*)&vc.z); acc4 += f.x; acc5 += f.y;
            f = __half22float2(*(const __half2*)&vc.w); acc6 += f.x; acc7 += f.y;
            f = __half22float2(*(const __half2*)&vd.x); acc0 += f.x; acc1 += f.y;
            f = __half22float2(*(const __half2*)&vd.y); acc2 += f.x; acc3 += f.y;
            f = __half22float2(*(const __half2*)&vd.z); acc4 += f.x; acc5 += f.y;
            f = __half22float2(*(const __half2*)&vd.w); acc6 += f.x; acc7 += f.y;
        }
        for (; j < s1; j++) {
            int sa = g_pay[j];
            uint4 va = *(const uint4*)(mb + (size_t)sa * 256 + base);
            float2 f;
            f = __half22float2(*(const __half2*)&va.x); acc0 += f.x; acc1 += f.y;
            f = __half22float2(*(const __half2*)&va.y); acc2 += f.x; acc3 += f.y;
            f = __half22float2(*(const __half2*)&va.z); acc4 += f.x; acc5 += f.y;
            f = __half22float2(*(const __half2*)&va.w); acc6 += f.x; acc7 += f.y;
        }
    }

    float c = ci[n];
    const float4* bb = (const float4*)(bias + base);
    float4 bv0 = bb[0], bv1 = bb[1];
    float4 o0, o1;
    o0.x = acc0 * c + bv0.x;  o0.y = acc1 * c + bv0.y;
    o0.z = acc2 * c + bv0.z;  o0.w = acc3 * c + bv0.w;
    o1.x = acc4 * c + bv1.x;  o1.y = acc5 * c + bv1.y;
    o1.z = acc6 * c + bv1.z;  o1.w = acc7 * c + bv1.w;
    float4* op = (float4*)(outh + (size_t)n * 256 + base);
    op[0] = o0;
    op[1] = o1;
}

// ---------------------------------------------------------------------------
extern "C" void kernel_launch(void* const* d_in, const int* in_sizes, int n_in,
                              void* d_out, int out_size) {
    const int*   drug_feat = (const int*)d_in[0];
    const int*   dis_feat  = (const int*)d_in[1];
    const int*   src       = (const int*)d_in[2];
    const int*   dst       = (const int*)d_in[3];
    const float* cj_drug   = (const float*)d_in[4];
    const float* ci_drug   = (const float*)d_in[5];
    const float* cj_dis    = (const float*)d_in[6];
    const float* ci_dis    = (const float*)d_in[7];
    const float* att       = (const float*)d_in[8];
    const float* basis     = (const float*)d_in[9];
    const float* fc_w      = (const float*)d_in[10];
    const float* fc_b      = (const float*)d_in[11];
    float* out = (float*)d_out;

    const int N   = in_sizes[4];
    const int E   = in_sizes[2] / RR;
    const int OUT = in_sizes[11];
    const int MU  = in_sizes[10] / (OUT * 3 * RR);
    const int IN  = in_sizes[9] / (BU * MU);
    const int nbins = NPART * N;

    // CSR build
    void* cntPtr = nullptr;
    cudaGetSymbolAddress(&cntPtr, g_cnt);
    cudaMemsetAsync(cntPtr, 0, (size_t)nbins * sizeof(int), 0);
    {
        int tot = NPART * E;
        k_hist<<<(tot + 255) / 256, 256>>>(src, dst, E, N);
    }
    {
        int nb = (nbins + 511) / 512;
        k_scan1<<<nb, 512>>>(nbins);
        k_scan2<<<1, 1024>>>(nb);
        k_scan3<<<(nbins + 255) / 256, 256>>>(nbins);
    }
    {
        int tot = NPART * E;
        k_place<<<(tot + 255) / 256, 256>>>(src, dst, E, N);
    }

    // Weights (fp16 P)
    k_P<<<RR * 3 * IN, OUT>>>(att, basis, fc_w, IN, MU, OUT);

    // Messages (both types, one launch)
    {
        long long warps = 2LL * N * RR;
        int mBlocks = (int)((warps * 32 + 255) / 256);
        k_m_all<<<mBlocks, 256>>>(drug_feat, dis_feat, cj_drug, cj_dis, N, IN);
    }

    const int gBlocks = (int)(((long long)N * 32 + 255) / 256);
    float* out_drug = out;
    float* out_dis  = out + (size_t)N * OUT;

    k_gather<<<gBlocks, 256>>>(0, ci_dis, fc_b, out_dis, N);   // drug -> dis
    k_gather<<<gBlocks, 256>>>(1, ci_drug, fc_b, out_drug, N); // dis -> drug
}

// round 6
// speedup vs baseline: 2.8136x; 1.0985x over previous
#include <cuda_runtime.h>
#include <cuda_fp16.h>
#include <cstdint>

#define RR 5
#define BU 4
#define MAX_IN 1024
#define MAX_MU 64
#define MAX_OUT 256
#define MAX_N 50000
#define MAX_E 500000
#define NPART (2 * RR)
#define NBINS (NPART * MAX_N)

// Static scratch
__device__ __half g_Ph[RR * 3 * MAX_IN * MAX_OUT];              // 7.9 MB fp16 P
__device__ __half g_mh[2][(size_t)RR * MAX_N * MAX_OUT];        // 2 x 128 MB fp16 messages
__device__ int    g_cnt[NBINS];
__device__ int    g_off[NBINS];      // scan1 incl -> scan3 excl -> place advances to END
__device__ int    g_pay[NPART * MAX_E];
__device__ int    g_bsum[1024];

// ---------------------------------------------------------------------------
// FA: fused k_P (blocks [0, pBlocks)) + vectorized hist (rest).
__global__ void k_fa(const float* __restrict__ att, const float* __restrict__ basis,
                     const float* __restrict__ fc_w,
                     const int* __restrict__ src, const int* __restrict__ dst,
                     int IN, int MU, int OUT, int E, int N, int pBlocks) {
    if ((int)blockIdx.x < pBlocks) {
        // ---- k_P: P[rk][i][o] = sum_m W[r][i][m] * fc_w[(rk*MU+m)*OUT+o]
        __shared__ float wrow[MAX_MU];
        int o  = threadIdx.x;
        int i  = blockIdx.x % IN;
        int rk = blockIdx.x / IN;
        int r  = rk / 3;
        if (o < MU) {
            float acc = 0.f;
#pragma unroll
            for (int b = 0; b < BU; b++)
                acc += att[r * BU + b] * basis[((size_t)b * IN + i) * MU + o];
            wrow[o] = acc;
        }
        __syncthreads();
        const float* fcb = fc_w + (size_t)(rk * MU) * OUT + o;
        float acc = 0.f;
#pragma unroll 8
        for (int m = 0; m < MU; m++)
            acc = fmaf(wrow[m], fcb[(size_t)m * OUT], acc);
        g_Ph[((size_t)rk * IN + i) * OUT + o] = __float2half_rn(acc);
    } else {
        // ---- hist: 2 edges per thread
        int t = (blockIdx.x - pBlocks) * blockDim.x + threadIdx.x;
        int eh = E >> 1;
        int half = NPART * eh;
        if (t >= half) return;
        int e2 = t % eh;
        int p  = t / eh;
        int r  = p % RR;
        const int* karr = (p < RR) ? dst : src;
        int2 kk = *(const int2*)(karr + (size_t)r * E + 2 * e2);
        atomicAdd(&g_cnt[p * N + kk.x], 1);
        atomicAdd(&g_cnt[p * N + kk.y], 1);
    }
}

// --------------------------- scan ------------------------------------------
__global__ void k_scan1(int n) {
    __shared__ int sh[512];
    int tid = threadIdx.x;
    int i = blockIdx.x * 512 + tid;
    int v = (i < n) ? g_cnt[i] : 0;
    sh[tid] = v;
    __syncthreads();
#pragma unroll
    for (int ofs = 1; ofs < 512; ofs <<= 1) {
        int t = (tid >= ofs) ? sh[tid - ofs] : 0;
        __syncthreads();
        sh[tid] += t;
        __syncthreads();
    }
    if (i < n) g_off[i] = sh[tid];           // inclusive, temp
    if (tid == 511) g_bsum[blockIdx.x] = sh[511];
}

// scan3': per-block reduce of block-sum prefix (scan2 eliminated)
__global__ void k_scan3(int n) {
    __shared__ int ssum[8];
    int tid = threadIdx.x;
    int blk = blockIdx.x >> 1;               // 256-block sits inside one 512-region
    int part = 0;
    for (int t = tid; t < blk; t += 256) part += g_bsum[t];
#pragma unroll
    for (int o = 16; o; o >>= 1) part += __shfl_down_sync(0xFFFFFFFFu, part, o);
    if ((tid & 31) == 0) ssum[tid >> 5] = part;
    __syncthreads();
    int S = 0;
#pragma unroll
    for (int w = 0; w < 8; w++) S += ssum[w];
    int i = blockIdx.x * 256 + tid;
    if (i < n) g_off[i] = g_off[i] - g_cnt[i] + S;   // exclusive offset
}

// ---------------------------------------------------------------------------
// FC: fused place (blocks [0, placeBlocks)) + k_m (rest).
// place: atomically advance g_off; afterwards g_off[bin] == END of bin.
// k_m: one warp per (type,node), loops 5 ratings.
__global__ void k_fc(const int* __restrict__ src, const int* __restrict__ dst,
                     const int* __restrict__ drug_feat, const int* __restrict__ dis_feat,
                     const float* __restrict__ cj_drug, const float* __restrict__ cj_dis,
                     int E, int N, int IN, int placeBlocks) {
    if ((int)blockIdx.x < placeBlocks) {
        int t = blockIdx.x * blockDim.x + threadIdx.x;
        int eh = E >> 1;
        int half = NPART * eh;
        if (t >= half) return;
        int e2 = t % eh;
        int p  = t / eh;
        int r  = p % RR;
        const int* karr = (p < RR) ? dst : src;
        const int* parr = (p < RR) ? src : dst;
        int2 kk = *(const int2*)(karr + (size_t)r * E + 2 * e2);
        int2 pp = *(const int2*)(parr + (size_t)r * E + 2 * e2);
        int pos0 = atomicAdd(&g_off[p * N + kk.x], 1);
        g_pay[pos0] = pp.x;
        int pos1 = atomicAdd(&g_off[p * N + kk.y], 1);
        g_pay[pos1] = pp.y;
    } else {
        int gw = ((blockIdx.x - placeBlocks) * blockDim.x + threadIdx.x) >> 5;
        int lane = threadIdx.x & 31;
        if (gw >= 2 * N) return;
        int type = gw >= N;
        int n = gw - type * N;
        const int* feat = type ? dis_feat : drug_feat;
        float c = (type ? cj_dis : cj_drug)[n];
        int f0 = feat[n * 3 + 0];
        int f1 = feat[n * 3 + 1];
        int f2 = feat[n * 3 + 2];
        int base = lane * 8;
        __half* mbase = g_mh[type] + (size_t)n * 256 + base;
#pragma unroll
        for (int r = 0; r < RR; r++) {
            uint4 ua = *(const uint4*)(g_Ph + ((size_t)(r * 3 + 0) * IN + f0) * 256 + base);
            uint4 ub = *(const uint4*)(g_Ph + ((size_t)(r * 3 + 1) * IN + f1) * 256 + base);
            uint4 ud = *(const uint4*)(g_Ph + ((size_t)(r * 3 + 2) * IN + f2) * 256 + base);
            uint4 pack;
            const unsigned int* pa = &ua.x;
            const unsigned int* pb = &ub.x;
            const unsigned int* pd = &ud.x;
            unsigned int* po = &pack.x;
#pragma unroll
            for (int q = 0; q < 4; q++) {
                float2 fa = __half22float2(*(const __half2*)&pa[q]);
                float2 fb = __half22float2(*(const __half2*)&pb[q]);
                float2 fd = __half22float2(*(const __half2*)&pd[q]);
                __half2 h = __floats2half2_rn(c * (fa.x + fb.x + fd.x),
                                              c * (fa.y + fb.y + fd.y));
                po[q] = *(const unsigned int*)&h;
            }
            *(uint4*)(mbase + (size_t)r * N * 256) = pack;
        }
    }
}

// ---------------------------------------------------------------------------
// Fused gather: both directions in one launch. One warp per (dir, node).
__global__ void k_gather(const float* __restrict__ ci_dis, const float* __restrict__ ci_drug,
                         const float* __restrict__ bias,
                         float* __restrict__ out, int N, int gBlocks) {
    int dir = (int)blockIdx.x >= gBlocks;
    int bb_ = blockIdx.x - dir * gBlocks;
    int n = (bb_ * blockDim.x + threadIdx.x) >> 5;
    int lane = threadIdx.x & 31;
    if (n >= N) return;
    int base = lane * 8;
    float acc0 = 0.f, acc1 = 0.f, acc2 = 0.f, acc3 = 0.f;
    float acc4 = 0.f, acc5 = 0.f, acc6 = 0.f, acc7 = 0.f;

#pragma unroll
    for (int r = 0; r < RR; r++) {
        int bin = (dir * RR + r) * N + n;
        int s1 = g_off[bin];                 // end (post-place)
        int s0 = s1 - g_cnt[bin];
        const __half* mb = g_mh[dir] + (size_t)r * N * 256;
        int j = s0;
        for (; j + 3 < s1; j += 4) {
            int sa = g_pay[j + 0];
            int sb = g_pay[j + 1];
            int sc = g_pay[j + 2];
            int sd = g_pay[j + 3];
            uint4 va = *(const uint4*)(mb + (size_t)sa * 256 + base);
            uint4 vb = *(const uint4*)(mb + (size_t)sb * 256 + base);
            uint4 vc = *(const uint4*)(mb + (size_t)sc * 256 + base);
            uint4 vd = *(const uint4*)(mb + (size_t)sd * 256 + base);
            float2 f;
            f = __half22float2(*(const __half2*)&va.x); acc0 += f.x; acc1 += f.y;
            f = __half22float2(*(const __half2*)&va.y); acc2 += f.x; acc3 += f.y;
            f = __half22float2(*(const __half2*)&va.z); acc4 += f.x; acc5 += f.y;
            f = __half22float2(*(const __half2*)&va.w); acc6 += f.x; acc7 += f.y;
            f = __half22float2(*(const __half2*)&vb.x); acc0 += f.x; acc1 += f.y;
            f = __half22float2(*(const __half2*)&vb.y); acc2 += f.x; acc3 += f.y;
            f = __half22float2(*(const __half2*)&vb.z); acc4 += f.x; acc5 += f.y;
            f = __half22float2(*(const __half2*)&vb.w); acc6 += f.x; acc7 += f.y;
            f = __half22float2(*(const __half2*)&vc.x); acc0 += f.x; acc1 += f.y;
            f = __half22float2(*(const __half2*)&vc.y); acc2 += f.x; acc3 += f.y;
            f = __half22float2(*(const __half2*)&vc.z); acc4 += f.x; acc5 += f.y;
            f = __half22float2(*(const __half2*)&vc.w); acc6 += f.x; acc7 += f.y;
            f = __half22float2(*(const __half2*)&vd.x); acc0 += f.x; acc1 += f.y;
            f = __half22float2(*(const __half2*)&vd.y); acc2 += f.x; acc3 += f.y;
            f = __half22float2(*(const __half2*)&vd.z); acc4 += f.x; acc5 += f.y;
            f = __half22float2(*(const __half2*)&vd.w); acc6 += f.x; acc7 += f.y;
        }
        for (; j < s1; j++) {
            int sa = g_pay[j];
            uint4 va = *(const uint4*)(mb + (size_t)sa * 256 + base);
            float2 f;
            f = __half22float2(*(const __half2*)&va.x); acc0 += f.x; acc1 += f.y;
            f = __half22float2(*(const __half2*)&va.y); acc2 += f.x; acc3 += f.y;
            f = __half22float2(*(const __half2*)&va.z); acc4 += f.x; acc5 += f.y;
            f = __half22float2(*(const __half2*)&va.w); acc6 += f.x; acc7 += f.y;
        }
    }

    // dir 0: drug->dis writes dis half with ci_dis; dir 1 writes drug half with ci_drug
    const float* ci = dir ? ci_drug : ci_dis;
    float* outh = out + (dir ? 0 : (size_t)N * 256);
    float c = ci[n];
    const float4* bv = (const float4*)(bias + base);
    float4 bv0 = bv[0], bv1 = bv[1];
    float4 o0, o1;
    o0.x = acc0 * c + bv0.x;  o0.y = acc1 * c + bv0.y;
    o0.z = acc2 * c + bv0.z;  o0.w = acc3 * c + bv0.w;
    o1.x = acc4 * c + bv1.x;  o1.y = acc5 * c + bv1.y;
    o1.z = acc6 * c + bv1.z;  o1.w = acc7 * c + bv1.w;
    float4* op = (float4*)(outh + (size_t)n * 256 + base);
    op[0] = o0;
    op[1] = o1;
}

// ---------------------------------------------------------------------------
extern "C" void kernel_launch(void* const* d_in, const int* in_sizes, int n_in,
                              void* d_out, int out_size) {
    const int*   drug_feat = (const int*)d_in[0];
    const int*   dis_feat  = (const int*)d_in[1];
    const int*   src       = (const int*)d_in[2];
    const int*   dst       = (const int*)d_in[3];
    const float* cj_drug   = (const float*)d_in[4];
    const float* ci_drug   = (const float*)d_in[5];
    const float* cj_dis    = (const float*)d_in[6];
    const float* ci_dis    = (const float*)d_in[7];
    const float* att       = (const float*)d_in[8];
    const float* basis     = (const float*)d_in[9];
    const float* fc_w      = (const float*)d_in[10];
    const float* fc_b      = (const float*)d_in[11];
    float* out = (float*)d_out;

    const int N   = in_sizes[4];
    const int E   = in_sizes[2] / RR;
    const int OUT = in_sizes[11];
    const int MU  = in_sizes[10] / (OUT * 3 * RR);
    const int IN  = in_sizes[9] / (BU * MU);
    const int nbins = NPART * N;

    void* cntPtr = nullptr;
    cudaGetSymbolAddress(&cntPtr, g_cnt);
    cudaMemsetAsync(cntPtr, 0, (size_t)nbins * sizeof(int), 0);

    // FA: k_P (pBlocks) + vectorized hist
    const int pBlocks = RR * 3 * IN;
    const int histThreads = NPART * (E >> 1);
    const int histBlocks = (histThreads + 255) / 256;
    k_fa<<<pBlocks + histBlocks, 256>>>(att, basis, fc_w, src, dst,
                                        IN, MU, OUT, E, N, pBlocks);

    // scan
    k_scan1<<<(nbins + 511) / 512, 512>>>(nbins);
    k_scan3<<<(nbins + 255) / 256, 256>>>(nbins);

    // FC: place (placeBlocks) + k_m (rest)
    const int placeBlocks = histBlocks;
    const int mBlocks = (int)(((long long)2 * N * 32 + 255) / 256);
    k_fc<<<placeBlocks + mBlocks, 256>>>(src, dst, drug_feat, dis_feat,
                                         cj_drug, cj_dis, E, N, IN, placeBlocks);

    // Fused gather (both directions)
    const int gBlocks = (int)(((long long)N * 32 + 255) / 256);
    k_gather<<<2 * gBlocks, 256>>>(ci_dis, ci_drug, fc_b, out, N, gBlocks);
}